// round 9
// baseline (speedup 1.0000x reference)
#include <cuda_runtime.h>
#include <cuda_bf16.h>
#include <stdint.h>

// PointPillars BEV scatter as a full-output gather.
//   out(B, C, H, W): out[b,c,y,x] = feat[map[b,y,x], c]  (or 0 if empty)
//
// R8: feature loads are per-lane PREDICATED (empty lanes issue no L1
// requests) instead of clamp+select; each thread handles TWO cell-quads
// (32 outputs) for ILP. Map cleared via cudaMemsetAsync node (0xFF == -1).

#define BEV_H 496
#define BEV_W 432
#define C_CH  64
#define HW    (BEV_H * BEV_W)     // 214,272
#define HW4   (HW / 4)            // 53,568
#define HW8   (HW / 8)            // 26,784  (W % 8 == 0)
#define MAXB  8

__device__ int g_pillar_map[MAXB * HW];

// ---------------------------------------------------------------------------
// Kernel 1: scatter pillar indices (collision-free coords by construction)
// ---------------------------------------------------------------------------
__global__ void scatter_map_kernel(const int* __restrict__ coords, int M) {
    int m = blockIdx.x * blockDim.x + threadIdx.x;
    if (m < M) {
        int b = coords[3 * m + 0];
        int y = coords[3 * m + 1];
        int x = coords[3 * m + 2];
        g_pillar_map[b * HW + y * BEV_W + x] = m;
    }
}

// ---------------------------------------------------------------------------
// Gather helper: one cell-quad x channel-quad patch.
// Predicated loads: empty lanes issue no L1 traffic.
// ---------------------------------------------------------------------------
__device__ __forceinline__ void do_quad(
    const float* __restrict__ feat, float* __restrict__ out,
    const int* __restrict__ map_q,   // &g_pillar_map[b*HW + 4*cellquad]
    long out_base,                   // (b*C + cbase)*HW + 4*cellquad
    int cbase)
{
    int4 m4 = *reinterpret_cast<const int4*>(map_q);

    float4 f0 = make_float4(0.f, 0.f, 0.f, 0.f);
    float4 f1 = f0, f2 = f0, f3 = f0;
    if (m4.x >= 0) f0 = __ldg(reinterpret_cast<const float4*>(&feat[m4.x * C_CH + cbase]));
    if (m4.y >= 0) f1 = __ldg(reinterpret_cast<const float4*>(&feat[m4.y * C_CH + cbase]));
    if (m4.z >= 0) f2 = __ldg(reinterpret_cast<const float4*>(&feat[m4.z * C_CH + cbase]));
    if (m4.w >= 0) f3 = __ldg(reinterpret_cast<const float4*>(&feat[m4.w * C_CH + cbase]));

    // Register 4x4 transpose: per-channel vectors over the 4 cells.
    float4 o0 = make_float4(f0.x, f1.x, f2.x, f3.x);
    float4 o1 = make_float4(f0.y, f1.y, f2.y, f3.y);
    float4 o2 = make_float4(f0.z, f1.z, f2.z, f3.z);
    float4 o3 = make_float4(f0.w, f1.w, f2.w, f3.w);

    __stcs(reinterpret_cast<float4*>(&out[out_base + 0L * HW]), o0);
    __stcs(reinterpret_cast<float4*>(&out[out_base + 1L * HW]), o1);
    __stcs(reinterpret_cast<float4*>(&out[out_base + 2L * HW]), o2);
    __stcs(reinterpret_cast<float4*>(&out[out_base + 3L * HW]), o3);
}

// ---------------------------------------------------------------------------
// Kernel 2: gather. Thread i -> (b, c4, r8) where r8 is a cell-OCTET (two
// adjacent quads, 8 cells): 2 independent map reads + <=8 predicated feat
// loads + 8 coalesced STG.128 streaming stores. 32 outputs per thread.
// ---------------------------------------------------------------------------
__global__ void __launch_bounds__(256) gather_out_kernel(
    const float* __restrict__ feat,   // (M, 64)
    float* __restrict__ out,          // (B, 64, H, W)
    int n32)                          // out_size / 32
{
    int i = blockIdx.x * blockDim.x + threadIdx.x;
    if (i >= n32) return;

    int r8 = i % HW8;                 // cell-octet index within plane
    int t  = i / HW8;                 // b*16 + c4
    int c4 = t & 15;
    int b  = t >> 4;

    int cbase   = c4 * 4;
    int cell0   = b * HW + 8 * r8;
    long obase  = (long)(b * C_CH + cbase) * HW + 8 * r8;

    do_quad(feat, out, &g_pillar_map[cell0],     obase,     cbase);
    do_quad(feat, out, &g_pillar_map[cell0 + 4], obase + 4, cbase);
}

// ---------------------------------------------------------------------------
// Launch
// Inputs: [0] voxel_coords (M,3) int32, [1] voxel_features (M,64) f32,
//         [2] batch_size scalar (B derived from out_size instead).
// Output: (B, 64, 496, 432) float32
// ---------------------------------------------------------------------------
extern "C" void kernel_launch(void* const* d_in, const int* in_sizes, int n_in,
                              void* d_out, int out_size) {
    const int*   coords = (const int*)d_in[0];
    const float* feat   = (const float*)d_in[1];
    float*       out    = (float*)d_out;

    int M = in_sizes[0] / 3;
    int B = out_size / (C_CH * HW);
    if (B < 1) B = 1;
    if (B > MAXB) B = MAXB;

    // Clear the map with a memset node: 0xFF bytes == -1 per int.
    void* map_ptr = nullptr;
    cudaGetSymbolAddress(&map_ptr, g_pillar_map);
    cudaMemsetAsync(map_ptr, 0xFF, (size_t)B * HW * sizeof(int), 0);

    scatter_map_kernel<<<(M + 255) / 256, 256>>>(coords, M);

    int n32 = out_size / 32;             // 1,714,176 for B=4
    gather_out_kernel<<<(n32 + 255) / 256, 256>>>(feat, out, n32);
}